// round 7
// baseline (speedup 1.0000x reference)
#include <cuda_runtime.h>

#define NS 512   // samples
#define DE 512   // embedding dim
#define NC 5     // classes
#define KSPLIT 8
#define KCHUNK (DE / KSPLIT)   // 64

// ---------------- device scratch (no allocation allowed) ----------------
__device__ float g_part[KSPLIT][NS * NS];  // raw partial dot products (8 MB)
__device__ float g_sum;                    // global loss sum
__device__ int   g_nz;                     // global nonzero count
__device__ int   g_done;                   // completed loss blocks

// ---------------- f32x2 packed helpers (sm_103a) ----------------
__device__ __forceinline__ unsigned long long dupf(float a) {
    unsigned long long d;
    asm("mov.b64 %0, {%1, %1};" : "=l"(d) : "f"(a));
    return d;
}
__device__ __forceinline__ unsigned long long fma2(unsigned long long a,
                                                   unsigned long long b,
                                                   unsigned long long c) {
    unsigned long long d;
    asm("fma.rn.f32x2 %0, %1, %2, %3;" : "=l"(d) : "l"(a), "l"(b), "l"(c));
    return d;
}
__device__ __forceinline__ float2 unpk(unsigned long long v) {
    float2 r;
    asm("mov.b64 {%0, %1}, %2;" : "=f"(r.x), "=f"(r.y) : "l"(v));
    return r;
}

// ---------------- kernel 1: partial-K raw dot GEMM ----------------
// 32x32 output tile, 64 threads, 4x4 micro-tile, f32x2 FMA.
// blockIdx.z selects K-chunk [z*64, z*64+64); partial written to g_part[z].
// Row norms are NOT computed here: ||x_i||^2 is the Gram diagonal, recovered
// in the loss kernel from sum_z g_part[z][i*NS+i].
__global__ void __launch_bounds__(64) gemm_kernel(const float* __restrict__ x) {
    __shared__ __align__(16) float As[32][36];  // [k][row]
    __shared__ __align__(16) float Bs[32][36];

    int t = threadIdx.x;           // 0..63
    int bi = blockIdx.y * 32;
    int bj = blockIdx.x * 32;
    int z = blockIdx.z;

    if (bi == 0 && bj == 0 && z == 0 && t == 0) {
        g_sum = 0.f; g_nz = 0; g_done = 0;   // re-zeroed on every graph replay
    }

    int tx = t & 7, ty = t >> 3;   // 8x8 micro grid
    int lrow = t >> 1;             // 0..31
    int lsel = t & 1;

    unsigned long long acc[4][2];
    #pragma unroll
    for (int r = 0; r < 4; r++) { acc[r][0] = 0ull; acc[r][1] = 0ull; }

    int kbeg = z * KCHUNK;
    #pragma unroll
    for (int k0 = kbeg; k0 < kbeg + KCHUNK; k0 += 32) {
        float4 a[4], b[4];
        const float4* gA = (const float4*)(x + (size_t)(bi + lrow) * DE + k0);
        const float4* gB = (const float4*)(x + (size_t)(bj + lrow) * DE + k0);
        #pragma unroll
        for (int q = 0; q < 4; q++) {
            a[q] = gA[lsel + 2 * q];
            b[q] = gB[lsel + 2 * q];
        }
        __syncthreads();
        #pragma unroll
        for (int q = 0; q < 4; q++) {
            int c = 4 * (lsel + 2 * q);
            As[c + 0][lrow] = a[q].x; As[c + 1][lrow] = a[q].y;
            As[c + 2][lrow] = a[q].z; As[c + 3][lrow] = a[q].w;
            Bs[c + 0][lrow] = b[q].x; Bs[c + 1][lrow] = b[q].y;
            Bs[c + 2][lrow] = b[q].z; Bs[c + 3][lrow] = b[q].w;
        }
        __syncthreads();
        #pragma unroll
        for (int kk = 0; kk < 32; kk++) {
            float4 av = *(const float4*)&As[kk][4 * ty];
            ulonglong2 bv = *(const ulonglong2*)&Bs[kk][4 * tx];
            unsigned long long a0 = dupf(av.x), a1 = dupf(av.y);
            unsigned long long a2 = dupf(av.z), a3 = dupf(av.w);
            acc[0][0] = fma2(a0, bv.x, acc[0][0]); acc[0][1] = fma2(a0, bv.y, acc[0][1]);
            acc[1][0] = fma2(a1, bv.x, acc[1][0]); acc[1][1] = fma2(a1, bv.y, acc[1][1]);
            acc[2][0] = fma2(a2, bv.x, acc[2][0]); acc[2][1] = fma2(a2, bv.y, acc[2][1]);
            acc[3][0] = fma2(a3, bv.x, acc[3][0]); acc[3][1] = fma2(a3, bv.y, acc[3][1]);
        }
    }

    float* dst = g_part[z];
    #pragma unroll
    for (int r = 0; r < 4; r++) {
        float2 p0 = unpk(acc[r][0]);
        float2 p1 = unpk(acc[r][1]);
        float4 o;
        o.x = p0.x; o.y = p0.y; o.z = p1.x; o.w = p1.y;
        *(float4*)&dst[(size_t)(bi + 4 * ty + r) * NS + bj + 4 * tx] = o;
    }
}

// ---------------- kernel 2: per-anchor loss + norms from diagonal + finalize ----
// one block per anchor i, 128 threads; thread t owns columns [4t, 4t+4)
__global__ void __launch_bounds__(128) loss_kernel(const float* __restrict__ dist_raw,
                                                   const int* __restrict__ target,
                                                   float* __restrict__ out) {
    __shared__ __align__(16) float bvals[NS];  // cos[i,j]+margin, or -1e30
    __shared__ __align__(16) float rns[NS];    // 1/max(||x_j||, 1e-8)
    __shared__ float crow[NS];
    __shared__ float cps[NS];
    __shared__ int klist[NS];
    __shared__ float cls_pos[NC];
    __shared__ int kcnt, scount;
    __shared__ float red_s[4];
    __shared__ int red_n[4];

    int i = blockIdx.x;
    int t = threadIdx.x;

    if (t == 0) {
        kcnt = 0; scount = 0;
        float c = 0.f;
        cls_pos[0] = 0.f;
        #pragma unroll
        for (int q = 0; q < NC - 1; q++) {
            c += log1pf(expf(dist_raw[q]));  // softplus cumsum
            cls_pos[q + 1] = c;
        }
    }

    // reconstruct 1/norm from Gram diagonal: ||x_j||^2 = sum_z part[z][j,j]
    #pragma unroll
    for (int q = 0; q < 4; q++) {
        int j = 4 * t + q;
        size_t doff = (size_t)j * NS + j;
        float s = 0.f;
        #pragma unroll
        for (int z = 0; z < KSPLIT; z++) s += g_part[z][doff];
        rns[j] = 1.0f / fmaxf(sqrtf(s), 1e-8f);
    }
    __syncthreads();

    // cos row i: sum 8 K-partials, scale by rn_i*rn_j
    float ri = rns[i];
    {
        size_t off = (size_t)i * NS + 4 * t;
        float sx = 0.f, sy = 0.f, sz = 0.f, sw = 0.f;
        #pragma unroll
        for (int z = 0; z < KSPLIT; z++) {
            float4 p = *(const float4*)&g_part[z][off];
            sx += p.x; sy += p.y; sz += p.z; sw += p.w;
        }
        float4 rj = *(const float4*)&rns[4 * t];
        float4 c;
        c.x = sx * ri * rj.x;
        c.y = sy * ri * rj.y;
        c.z = sz * ri * rj.z;
        c.w = sw * ri * rj.w;
        *(float4*)&crow[4 * t] = c;
        int4 tg = *(const int4*)&target[4 * t];
        cps[4 * t + 0] = cls_pos[tg.x];
        cps[4 * t + 1] = cls_pos[tg.y];
        cps[4 * t + 2] = cls_pos[tg.z];
        cps[4 * t + 3] = cls_pos[tg.w];
    }
    __syncthreads();

    float cpi = cps[i];
    int myc = 0;
    #pragma unroll
    for (int q = 0; q < 4; q++) {
        int j = 4 * t + q;
        float m = fabsf(cpi - cps[j]);
        bool same = (m == 0.0f);  // class_pos strictly increasing -> equality iff same class
        bvals[j] = same ? -1e30f : (crow[j] + m);
        if (same) {
            myc++;
            if (j != i) klist[atomicAdd(&kcnt, 1)] = j;
        }
    }
    atomicAdd(&scount, myc);
    __syncthreads();

    int nk = kcnt;
    int negc = NS - scount;
    float inv = 1.0f / (float)(negc > 1 ? negc : 1);

    float lsum = 0.f;
    int lnz = 0;
    const float4* bv4 = (const float4*)bvals;
    for (int p = t; p < nk; p += 128) {
        float cik = crow[klist[p]];
        float acc0 = 0.f, acc1 = 0.f;
        #pragma unroll 8
        for (int jj = 0; jj < NS / 4; jj++) {
            float4 bv = bv4[jj];
            acc0 += fmaxf(bv.x - cik, 0.f) + fmaxf(bv.y - cik, 0.f);
            acc1 += fmaxf(bv.z - cik, 0.f) + fmaxf(bv.w - cik, 0.f);
        }
        float acc = acc0 + acc1;
        lsum += acc * inv;
        lnz += (acc != 0.f) ? 1 : 0;
    }

    // block reduce (4 warps)
    for (int o = 16; o > 0; o >>= 1) {
        lsum += __shfl_down_sync(0xffffffffu, lsum, o);
        lnz += __shfl_down_sync(0xffffffffu, lnz, o);
    }
    int wid = t >> 5, lid = t & 31;
    if (lid == 0) { red_s[wid] = lsum; red_n[wid] = lnz; }
    __syncthreads();

    // fused finalize: last block to finish computes the output
    if (t == 0) {
        float bs = red_s[0] + red_s[1] + red_s[2] + red_s[3];
        int bn = red_n[0] + red_n[1] + red_n[2] + red_n[3];
        atomicAdd(&g_sum, bs);
        atomicAdd(&g_nz, bn);
        __threadfence();
        if (atomicAdd(&g_done, 1) == NS - 1) {
            __threadfence();
            float S = atomicAdd(&g_sum, 0.0f);   // atomic read after all adds visible
            int N = atomicAdd(&g_nz, 0);
            out[0] = S / (float)(N > 1 ? N : 1);
        }
    }
}

extern "C" void kernel_launch(void* const* d_in, const int* in_sizes, int n_in,
                              void* d_out, int out_size) {
    const float* pred = (const float*)d_in[0];   // [512, 512] f32
    const float* draw = (const float*)d_in[1];   // [4] f32
    const int* target = (const int*)d_in[2];     // [512] i32
    float* out = (float*)d_out;

    gemm_kernel<<<dim3(16, 16, KSPLIT), 64>>>(pred);
    loss_kernel<<<NS, 128>>>(draw, target, out);
}

// round 8
// speedup vs baseline: 1.1532x; 1.1532x over previous
#include <cuda_runtime.h>

#define NS 512   // samples
#define DE 512   // embedding dim
#define NC 5     // classes
#define KSPLIT 8
#define KCHUNK (DE / KSPLIT)   // 64

// ---------------- device scratch (no allocation allowed) ----------------
__device__ float g_part[KSPLIT][NS * NS];  // raw partial dot products (8 MB)
__device__ float g_diag[KSPLIT][NS];       // compact Gram-diagonal partials
__device__ float g_sum;                    // global loss sum
__device__ int   g_nz;                     // global nonzero count
__device__ int   g_done;                   // completed loss blocks

// ---------------- f32x2 packed helpers (sm_103a) ----------------
__device__ __forceinline__ unsigned long long dupf(float a) {
    unsigned long long d;
    asm("mov.b64 %0, {%1, %1};" : "=l"(d) : "f"(a));
    return d;
}
__device__ __forceinline__ unsigned long long fma2(unsigned long long a,
                                                   unsigned long long b,
                                                   unsigned long long c) {
    unsigned long long d;
    asm("fma.rn.f32x2 %0, %1, %2, %3;" : "=l"(d) : "l"(a), "l"(b), "l"(c));
    return d;
}
__device__ __forceinline__ float2 unpk(unsigned long long v) {
    float2 r;
    asm("mov.b64 {%0, %1}, %2;" : "=f"(r.x), "=f"(r.y) : "l"(v));
    return r;
}

// ---------------- kernel 1: partial-K raw dot GEMM ----------------
// 32x32 output tile, 64 threads, 4x4 micro-tile, f32x2 FMA.
// blockIdx.z selects K-chunk [z*64, z*64+64); partial written to g_part[z].
// Diagonal blocks (bi==bj) additionally export the Gram diagonal compactly
// to g_diag[z][*] so the loss kernel can rebuild row norms coalesced.
__global__ void __launch_bounds__(64) gemm_kernel(const float* __restrict__ x) {
    __shared__ __align__(16) float As[32][36];  // [k][row]
    __shared__ __align__(16) float Bs[32][36];

    int t = threadIdx.x;           // 0..63
    int bi = blockIdx.y * 32;
    int bj = blockIdx.x * 32;
    int z = blockIdx.z;

    if (bi == 0 && bj == 0 && z == 0 && t == 0) {
        g_sum = 0.f; g_nz = 0; g_done = 0;   // re-zeroed on every graph replay
    }

    int tx = t & 7, ty = t >> 3;   // 8x8 micro grid
    int lrow = t >> 1;             // 0..31
    int lsel = t & 1;

    unsigned long long acc[4][2];
    #pragma unroll
    for (int r = 0; r < 4; r++) { acc[r][0] = 0ull; acc[r][1] = 0ull; }

    int kbeg = z * KCHUNK;
    #pragma unroll
    for (int k0 = kbeg; k0 < kbeg + KCHUNK; k0 += 32) {
        float4 a[4], b[4];
        const float4* gA = (const float4*)(x + (size_t)(bi + lrow) * DE + k0);
        const float4* gB = (const float4*)(x + (size_t)(bj + lrow) * DE + k0);
        #pragma unroll
        for (int q = 0; q < 4; q++) {
            a[q] = gA[lsel + 2 * q];
            b[q] = gB[lsel + 2 * q];
        }
        __syncthreads();
        #pragma unroll
        for (int q = 0; q < 4; q++) {
            int c = 4 * (lsel + 2 * q);
            As[c + 0][lrow] = a[q].x; As[c + 1][lrow] = a[q].y;
            As[c + 2][lrow] = a[q].z; As[c + 3][lrow] = a[q].w;
            Bs[c + 0][lrow] = b[q].x; Bs[c + 1][lrow] = b[q].y;
            Bs[c + 2][lrow] = b[q].z; Bs[c + 3][lrow] = b[q].w;
        }
        __syncthreads();
        #pragma unroll
        for (int kk = 0; kk < 32; kk++) {
            float4 av = *(const float4*)&As[kk][4 * ty];
            ulonglong2 bv = *(const ulonglong2*)&Bs[kk][4 * tx];
            unsigned long long a0 = dupf(av.x), a1 = dupf(av.y);
            unsigned long long a2 = dupf(av.z), a3 = dupf(av.w);
            acc[0][0] = fma2(a0, bv.x, acc[0][0]); acc[0][1] = fma2(a0, bv.y, acc[0][1]);
            acc[1][0] = fma2(a1, bv.x, acc[1][0]); acc[1][1] = fma2(a1, bv.y, acc[1][1]);
            acc[2][0] = fma2(a2, bv.x, acc[2][0]); acc[2][1] = fma2(a2, bv.y, acc[2][1]);
            acc[3][0] = fma2(a3, bv.x, acc[3][0]); acc[3][1] = fma2(a3, bv.y, acc[3][1]);
        }
    }

    float* dst = g_part[z];
    bool diag = (bi == bj) && (tx == ty);
    #pragma unroll
    for (int r = 0; r < 4; r++) {
        float2 p0 = unpk(acc[r][0]);
        float2 p1 = unpk(acc[r][1]);
        float4 o;
        o.x = p0.x; o.y = p0.y; o.z = p1.x; o.w = p1.y;
        *(float4*)&dst[(size_t)(bi + 4 * ty + r) * NS + bj + 4 * tx] = o;
        if (diag) {
            float dval = (r == 0) ? o.x : (r == 1) ? o.y : (r == 2) ? o.z : o.w;
            g_diag[z][bi + 4 * ty + r] = dval;
        }
    }
}

// ---------------- kernel 2: per-anchor loss + norms from g_diag + finalize ----
// one block per anchor i, 128 threads; thread t owns columns [4t, 4t+4)
__global__ void __launch_bounds__(128) loss_kernel(const float* __restrict__ dist_raw,
                                                   const int* __restrict__ target,
                                                   float* __restrict__ out) {
    __shared__ __align__(16) float bvals[NS];  // cos[i,j]+margin, or -1e30
    __shared__ __align__(16) float rns[NS];    // 1/max(||x_j||, 1e-8)
    __shared__ float crow[NS];
    __shared__ float cps[NS];
    __shared__ int klist[NS];
    __shared__ float cls_pos[NC];
    __shared__ int kcnt, scount;
    __shared__ float red_s[4];
    __shared__ int red_n[4];

    int i = blockIdx.x;
    int t = threadIdx.x;

    if (t == 0) {
        kcnt = 0; scount = 0;
        float c = 0.f;
        cls_pos[0] = 0.f;
        #pragma unroll
        for (int q = 0; q < NC - 1; q++) {
            c += log1pf(expf(dist_raw[q]));  // softplus cumsum
            cls_pos[q + 1] = c;
        }
    }

    // reconstruct 1/norm from compact diagonal partials (coalesced float4)
    {
        float sx = 0.f, sy = 0.f, sz = 0.f, sw = 0.f;
        #pragma unroll
        for (int z = 0; z < KSPLIT; z++) {
            float4 p = *(const float4*)&g_diag[z][4 * t];
            sx += p.x; sy += p.y; sz += p.z; sw += p.w;
        }
        rns[4 * t + 0] = 1.0f / fmaxf(sqrtf(sx), 1e-8f);
        rns[4 * t + 1] = 1.0f / fmaxf(sqrtf(sy), 1e-8f);
        rns[4 * t + 2] = 1.0f / fmaxf(sqrtf(sz), 1e-8f);
        rns[4 * t + 3] = 1.0f / fmaxf(sqrtf(sw), 1e-8f);
    }
    __syncthreads();

    // cos row i: sum 8 K-partials, scale by rn_i*rn_j
    float ri = rns[i];
    {
        size_t off = (size_t)i * NS + 4 * t;
        float sx = 0.f, sy = 0.f, sz = 0.f, sw = 0.f;
        #pragma unroll
        for (int z = 0; z < KSPLIT; z++) {
            float4 p = *(const float4*)&g_part[z][off];
            sx += p.x; sy += p.y; sz += p.z; sw += p.w;
        }
        float4 rj = *(const float4*)&rns[4 * t];
        float4 c;
        c.x = sx * ri * rj.x;
        c.y = sy * ri * rj.y;
        c.z = sz * ri * rj.z;
        c.w = sw * ri * rj.w;
        *(float4*)&crow[4 * t] = c;
        int4 tg = *(const int4*)&target[4 * t];
        cps[4 * t + 0] = cls_pos[tg.x];
        cps[4 * t + 1] = cls_pos[tg.y];
        cps[4 * t + 2] = cls_pos[tg.z];
        cps[4 * t + 3] = cls_pos[tg.w];
    }
    __syncthreads();

    float cpi = cps[i];
    int myc = 0;
    #pragma unroll
    for (int q = 0; q < 4; q++) {
        int j = 4 * t + q;
        float m = fabsf(cpi - cps[j]);
        bool same = (m == 0.0f);  // class_pos strictly increasing -> equality iff same class
        bvals[j] = same ? -1e30f : (crow[j] + m);
        if (same) {
            myc++;
            if (j != i) klist[atomicAdd(&kcnt, 1)] = j;
        }
    }
    atomicAdd(&scount, myc);
    __syncthreads();

    int nk = kcnt;
    int negc = NS - scount;
    float inv = 1.0f / (float)(negc > 1 ? negc : 1);

    float lsum = 0.f;
    int lnz = 0;
    const float4* bv4 = (const float4*)bvals;
    for (int p = t; p < nk; p += 128) {
        float cik = crow[klist[p]];
        float acc0 = 0.f, acc1 = 0.f;
        #pragma unroll 8
        for (int jj = 0; jj < NS / 4; jj++) {
            float4 bv = bv4[jj];
            acc0 += fmaxf(bv.x - cik, 0.f) + fmaxf(bv.y - cik, 0.f);
            acc1 += fmaxf(bv.z - cik, 0.f) + fmaxf(bv.w - cik, 0.f);
        }
        float acc = acc0 + acc1;
        lsum += acc * inv;
        lnz += (acc != 0.f) ? 1 : 0;
    }

    // block reduce (4 warps)
    for (int o = 16; o > 0; o >>= 1) {
        lsum += __shfl_down_sync(0xffffffffu, lsum, o);
        lnz += __shfl_down_sync(0xffffffffu, lnz, o);
    }
    int wid = t >> 5, lid = t & 31;
    if (lid == 0) { red_s[wid] = lsum; red_n[wid] = lnz; }
    __syncthreads();

    // fused finalize: last block to finish computes the output
    if (t == 0) {
        float bs = red_s[0] + red_s[1] + red_s[2] + red_s[3];
        int bn = red_n[0] + red_n[1] + red_n[2] + red_n[3];
        atomicAdd(&g_sum, bs);
        atomicAdd(&g_nz, bn);
        __threadfence();
        if (atomicAdd(&g_done, 1) == NS - 1) {
            __threadfence();
            float S = atomicAdd(&g_sum, 0.0f);   // atomic read after all adds visible
            int N = atomicAdd(&g_nz, 0);
            out[0] = S / (float)(N > 1 ? N : 1);
        }
    }
}

extern "C" void kernel_launch(void* const* d_in, const int* in_sizes, int n_in,
                              void* d_out, int out_size) {
    const float* pred = (const float*)d_in[0];   // [512, 512] f32
    const float* draw = (const float*)d_in[1];   // [4] f32
    const int* target = (const int*)d_in[2];     // [512] i32
    float* out = (float*)d_out;

    gemm_kernel<<<dim3(16, 16, KSPLIT), 64>>>(pred);
    loss_kernel<<<NS, 128>>>(draw, target, out);
}

// round 9
// speedup vs baseline: 1.1655x; 1.0106x over previous
#include <cuda_runtime.h>

#define NS 512   // samples
#define DE 512   // embedding dim
#define NC 5     // classes
#define KSPLIT 4
#define NBLK 512

// ---------------- device scratch (no allocation allowed) ----------------
__device__ float g_part[KSPLIT][NS * NS];  // raw partial dot products (4 MB)
__device__ float g_rn[NS];                 // 1 / max(row_norm, 1e-8)
__device__ float g_sum;                    // global loss sum
__device__ int   g_nz;                     // global nonzero count
__device__ int   g_done;                   // completed blocks (phase 2)
__device__ int   g_bar;                    // grid barrier arrivals

// ---------------- f32x2 packed helpers (sm_103a) ----------------
__device__ __forceinline__ unsigned long long dupf(float a) {
    unsigned long long d;
    asm("mov.b64 %0, {%1, %1};" : "=l"(d) : "f"(a));
    return d;
}
__device__ __forceinline__ unsigned long long fma2(unsigned long long a,
                                                   unsigned long long b,
                                                   unsigned long long c) {
    unsigned long long d;
    asm("fma.rn.f32x2 %0, %1, %2, %3;" : "=l"(d) : "l"(a), "l"(b), "l"(c));
    return d;
}
__device__ __forceinline__ float2 unpk(unsigned long long v) {
    float2 r;
    asm("mov.b64 {%0, %1}, %2;" : "=f"(r.x), "=f"(r.y) : "l"(v));
    return r;
}

// ---------------- shared memory: phases alias via union ----------------
struct GemmS {
    float As[32][68];   // [k][row], 64 rows + pad
    float Bs[32][36];   // [k][row], 32 rows + pad
};
struct LossS {
    float bvals[NS];
    float crow[NS];
    float cps[NS];
    int   klist[NS];
};

// ---------------- single persistent kernel ----------------
// 512 blocks x 128 threads, all co-resident (148 SMs x 4 blocks = 592 slots).
// phase0: row norm for row=blk. phase1: one 64x32xK128 gemm tile.
// grid barrier. phase2: per-anchor loss for i=blk + fused finalize/reset.
__global__ void __launch_bounds__(128, 4)
fused_kernel(const float* __restrict__ x,
             const float* __restrict__ dist_raw,
             const int* __restrict__ target,
             float* __restrict__ out) {
    __shared__ __align__(16) union { GemmS g; LossS l; } sm;
    __shared__ float cls_pos[NC];
    __shared__ float red_s[4];
    __shared__ int red_n[4];
    __shared__ int kcnt, scount;

    int blk = blockIdx.x;
    int t = threadIdx.x;
    int wid = t >> 5, lid = t & 31;

    // ---------- phase 0: 1/norm of row blk ----------
    {
        float4 v = ((const float4*)x)[(size_t)blk * (DE / 4) + t];
        float s = v.x * v.x + v.y * v.y + v.z * v.z + v.w * v.w;
        for (int o = 16; o > 0; o >>= 1) s += __shfl_down_sync(0xffffffffu, s, o);
        if (lid == 0) red_s[wid] = s;
        __syncthreads();
        if (t == 0) {
            float nrm = sqrtf(red_s[0] + red_s[1] + red_s[2] + red_s[3]);
            g_rn[blk] = 1.0f / fmaxf(nrm, 1e-8f);
        }
    }

    // ---------- phase 1: gemm tile 64x32, K-chunk 128 ----------
    {
        int z = blk & 3;               // K chunk
        int bj = (blk >> 2) & 15;      // col tile (32)
        int bi = blk >> 6;             // row tile (64)
        int tx = t & 7, ty = t >> 3;   // 8x16 micro grid, 4x4 each
        int arow = t >> 1, asel = t & 1;   // A loads: 2 thr/row, 4 f4
        int brow = t >> 2, bsel = t & 3;   // B loads: 4 thr/row, 2 f4

        unsigned long long acc[4][2];
        #pragma unroll
        for (int r = 0; r < 4; r++) { acc[r][0] = 0ull; acc[r][1] = 0ull; }

        int kbeg = z * 128;
        #pragma unroll 1
        for (int k0 = kbeg; k0 < kbeg + 128; k0 += 32) {
            float4 a[4], b[2];
            const float4* gA = (const float4*)(x + (size_t)(bi * 64 + arow) * DE + k0);
            #pragma unroll
            for (int q = 0; q < 4; q++) a[q] = gA[asel + 2 * q];
            const float4* gB = (const float4*)(x + (size_t)(bj * 32 + brow) * DE + k0);
            #pragma unroll
            for (int q = 0; q < 2; q++) b[q] = gB[bsel + 4 * q];
            __syncthreads();
            #pragma unroll
            for (int q = 0; q < 4; q++) {
                int c = 4 * (asel + 2 * q);
                sm.g.As[c + 0][arow] = a[q].x; sm.g.As[c + 1][arow] = a[q].y;
                sm.g.As[c + 2][arow] = a[q].z; sm.g.As[c + 3][arow] = a[q].w;
            }
            #pragma unroll
            for (int q = 0; q < 2; q++) {
                int c = 4 * (bsel + 4 * q);
                sm.g.Bs[c + 0][brow] = b[q].x; sm.g.Bs[c + 1][brow] = b[q].y;
                sm.g.Bs[c + 2][brow] = b[q].z; sm.g.Bs[c + 3][brow] = b[q].w;
            }
            __syncthreads();
            #pragma unroll
            for (int kk = 0; kk < 32; kk++) {
                float4 av = *(const float4*)&sm.g.As[kk][4 * ty];
                ulonglong2 bv = *(const ulonglong2*)&sm.g.Bs[kk][4 * tx];
                unsigned long long a0 = dupf(av.x), a1 = dupf(av.y);
                unsigned long long a2 = dupf(av.z), a3 = dupf(av.w);
                acc[0][0] = fma2(a0, bv.x, acc[0][0]); acc[0][1] = fma2(a0, bv.y, acc[0][1]);
                acc[1][0] = fma2(a1, bv.x, acc[1][0]); acc[1][1] = fma2(a1, bv.y, acc[1][1]);
                acc[2][0] = fma2(a2, bv.x, acc[2][0]); acc[2][1] = fma2(a2, bv.y, acc[2][1]);
                acc[3][0] = fma2(a3, bv.x, acc[3][0]); acc[3][1] = fma2(a3, bv.y, acc[3][1]);
            }
        }

        float* dst = g_part[z];
        #pragma unroll
        for (int r = 0; r < 4; r++) {
            float2 p0 = unpk(acc[r][0]);
            float2 p1 = unpk(acc[r][1]);
            float4 o;
            o.x = p0.x; o.y = p0.y; o.z = p1.x; o.w = p1.y;
            *(float4*)&dst[(size_t)(bi * 64 + 4 * ty + r) * NS + bj * 32 + 4 * tx] = o;
        }
    }

    // ---------- grid barrier (all 512 blocks co-resident) ----------
    __syncthreads();
    __threadfence();                       // release g_part / g_rn
    if (t == 0) {
        atomicAdd(&g_bar, 1);
        while (*(volatile int*)&g_bar < NBLK) __nanosleep(32);
    }
    __syncthreads();
    __threadfence();                       // acquire

    // ---------- phase 2: per-anchor loss for i = blk ----------
    int i = blk;
    if (t == 0) {
        kcnt = 0; scount = 0;
        float c = 0.f;
        cls_pos[0] = 0.f;
        #pragma unroll
        for (int q = 0; q < NC - 1; q++) {
            c += log1pf(expf(dist_raw[q]));  // softplus cumsum
            cls_pos[q + 1] = c;
        }
    }
    __syncthreads();

    float ri = g_rn[i];
    {
        size_t off = (size_t)i * NS + 4 * t;
        float sx = 0.f, sy = 0.f, szv = 0.f, sw = 0.f;
        #pragma unroll
        for (int z = 0; z < KSPLIT; z++) {
            float4 p = *(const float4*)&g_part[z][off];
            sx += p.x; sy += p.y; szv += p.z; sw += p.w;
        }
        float4 rj = *(const float4*)&g_rn[4 * t];
        float4 c;
        c.x = sx * ri * rj.x;
        c.y = sy * ri * rj.y;
        c.z = szv * ri * rj.z;
        c.w = sw * ri * rj.w;
        *(float4*)&sm.l.crow[4 * t] = c;
        int4 tg = *(const int4*)&target[4 * t];
        sm.l.cps[4 * t + 0] = cls_pos[tg.x];
        sm.l.cps[4 * t + 1] = cls_pos[tg.y];
        sm.l.cps[4 * t + 2] = cls_pos[tg.z];
        sm.l.cps[4 * t + 3] = cls_pos[tg.w];
    }
    __syncthreads();

    float cpi = sm.l.cps[i];
    int myc = 0;
    #pragma unroll
    for (int q = 0; q < 4; q++) {
        int j = 4 * t + q;
        float m = fabsf(cpi - sm.l.cps[j]);
        bool same = (m == 0.0f);  // class_pos strictly increasing -> equality iff same class
        sm.l.bvals[j] = same ? -1e30f : (sm.l.crow[j] + m);
        if (same) {
            myc++;
            if (j != i) sm.l.klist[atomicAdd(&kcnt, 1)] = j;
        }
    }
    atomicAdd(&scount, myc);
    __syncthreads();

    int nk = kcnt;
    int negc = NS - scount;
    float inv = 1.0f / (float)(negc > 1 ? negc : 1);

    float lsum = 0.f;
    int lnz = 0;
    const float4* bv4 = (const float4*)sm.l.bvals;
    for (int p = t; p < nk; p += 128) {
        float cik = sm.l.crow[sm.l.klist[p]];
        float acc0 = 0.f, acc1 = 0.f;
        #pragma unroll 8
        for (int jj = 0; jj < NS / 4; jj++) {
            float4 bv = bv4[jj];
            acc0 += fmaxf(bv.x - cik, 0.f) + fmaxf(bv.y - cik, 0.f);
            acc1 += fmaxf(bv.z - cik, 0.f) + fmaxf(bv.w - cik, 0.f);
        }
        float acc = acc0 + acc1;
        lsum += acc * inv;
        lnz += (acc != 0.f) ? 1 : 0;
    }

    for (int o = 16; o > 0; o >>= 1) {
        lsum += __shfl_down_sync(0xffffffffu, lsum, o);
        lnz += __shfl_down_sync(0xffffffffu, lnz, o);
    }
    if (lid == 0) { red_s[wid] = lsum; red_n[wid] = lnz; }
    __syncthreads();

    // fused finalize: last block computes output and resets state for replay
    if (t == 0) {
        float bs = red_s[0] + red_s[1] + red_s[2] + red_s[3];
        int bn = red_n[0] + red_n[1] + red_n[2] + red_n[3];
        atomicAdd(&g_sum, bs);
        atomicAdd(&g_nz, bn);
        __threadfence();
        if (atomicAdd(&g_done, 1) == NBLK - 1) {
            __threadfence();
            float S = *(volatile float*)&g_sum;
            int N = *(volatile int*)&g_nz;
            out[0] = S / (float)(N > 1 ? N : 1);
            // reset for next graph replay (all blocks already past barrier & done)
            g_sum = 0.f; g_nz = 0; g_done = 0; g_bar = 0;
            __threadfence();
        }
    }
}

extern "C" void kernel_launch(void* const* d_in, const int* in_sizes, int n_in,
                              void* d_out, int out_size) {
    const float* pred = (const float*)d_in[0];   // [512, 512] f32
    const float* draw = (const float*)d_in[1];   // [4] f32
    const int* target = (const int*)d_in[2];     // [512] i32
    float* out = (float*)d_out;

    fused_kernel<<<NBLK, 128>>>(pred, draw, target, out);
}

// round 10
// speedup vs baseline: 1.2940x; 1.1102x over previous
#include <cuda_runtime.h>

#define NS 512   // samples
#define DE 512   // embedding dim
#define NC 5     // classes
#define KSPLIT 8
#define KCHUNK (DE / KSPLIT)   // 64

// ---------------- device scratch (no allocation allowed) ----------------
__device__ __align__(16) float g_part[KSPLIT][NS * NS];  // raw partial dots (8 MB)
__device__ __align__(16) float g_diag[KSPLIT][NS];       // compact Gram-diagonal partials
__device__ float g_sum;                    // global loss sum
__device__ int   g_nz;                     // global nonzero count
__device__ int   g_done;                   // completed loss blocks

// ---------------- f32x2 packed helpers (sm_103a) ----------------
__device__ __forceinline__ unsigned long long dupf(float a) {
    unsigned long long d;
    asm("mov.b64 %0, {%1, %1};" : "=l"(d) : "f"(a));
    return d;
}
__device__ __forceinline__ unsigned long long fma2(unsigned long long a,
                                                   unsigned long long b,
                                                   unsigned long long c) {
    unsigned long long d;
    asm("fma.rn.f32x2 %0, %1, %2, %3;" : "=l"(d) : "l"(a), "l"(b), "l"(c));
    return d;
}
__device__ __forceinline__ float2 unpk(unsigned long long v) {
    float2 r;
    asm("mov.b64 {%0, %1}, %2;" : "=f"(r.x), "=f"(r.y) : "l"(v));
    return r;
}

// ---------------- kernel 1: partial-K raw dot GEMM ----------------
// 64x32 output tile, 128 threads, 4x4 micro-tile, f32x2 FMA, KCHUNK=64.
// grid (16 bj, 8 bi, 8 z) = 1024 blocks -> ~6.9 warps/SMSP for latency hiding.
// Diagonal-covering blocks also export the Gram diagonal compactly to g_diag.
__global__ void __launch_bounds__(128) gemm_kernel(const float* __restrict__ x) {
    __shared__ __align__(16) float As[32][68];  // [k][row], 64 rows + pad
    __shared__ __align__(16) float Bs[32][36];  // [k][row], 32 rows + pad

    int t = threadIdx.x;           // 0..127
    int bj = blockIdx.x;           // col tile (32 wide)
    int bi = blockIdx.y;           // row tile (64 tall)
    int z = blockIdx.z;            // K chunk

    if (bj == 0 && bi == 0 && z == 0 && t == 0) {
        g_sum = 0.f; g_nz = 0; g_done = 0;   // re-zeroed on every graph replay
    }

    int tx = t & 7, ty = t >> 3;       // 8x16 micro grid, 4x4 each
    int arow = t >> 1, asel = t & 1;   // A loads: 2 thr/row, 4 f4 each
    int brow = t >> 2, bsel = t & 3;   // B loads: 4 thr/row, 2 f4 each

    unsigned long long acc[4][2];
    #pragma unroll
    for (int r = 0; r < 4; r++) { acc[r][0] = 0ull; acc[r][1] = 0ull; }

    int kbeg = z * KCHUNK;
    #pragma unroll
    for (int k0 = kbeg; k0 < kbeg + KCHUNK; k0 += 32) {
        float4 a[4], b[2];
        const float4* gA = (const float4*)(x + (size_t)(bi * 64 + arow) * DE + k0);
        #pragma unroll
        for (int q = 0; q < 4; q++) a[q] = gA[asel + 2 * q];
        const float4* gB = (const float4*)(x + (size_t)(bj * 32 + brow) * DE + k0);
        #pragma unroll
        for (int q = 0; q < 2; q++) b[q] = gB[bsel + 4 * q];
        __syncthreads();
        #pragma unroll
        for (int q = 0; q < 4; q++) {
            int c = 4 * (asel + 2 * q);
            As[c + 0][arow] = a[q].x; As[c + 1][arow] = a[q].y;
            As[c + 2][arow] = a[q].z; As[c + 3][arow] = a[q].w;
        }
        #pragma unroll
        for (int q = 0; q < 2; q++) {
            int c = 4 * (bsel + 4 * q);
            Bs[c + 0][brow] = b[q].x; Bs[c + 1][brow] = b[q].y;
            Bs[c + 2][brow] = b[q].z; Bs[c + 3][brow] = b[q].w;
        }
        __syncthreads();
        #pragma unroll
        for (int kk = 0; kk < 32; kk++) {
            float4 av = *(const float4*)&As[kk][4 * ty];
            ulonglong2 bv = *(const ulonglong2*)&Bs[kk][4 * tx];
            unsigned long long a0 = dupf(av.x), a1 = dupf(av.y);
            unsigned long long a2 = dupf(av.z), a3 = dupf(av.w);
            acc[0][0] = fma2(a0, bv.x, acc[0][0]); acc[0][1] = fma2(a0, bv.y, acc[0][1]);
            acc[1][0] = fma2(a1, bv.x, acc[1][0]); acc[1][1] = fma2(a1, bv.y, acc[1][1]);
            acc[2][0] = fma2(a2, bv.x, acc[2][0]); acc[2][1] = fma2(a2, bv.y, acc[2][1]);
            acc[3][0] = fma2(a3, bv.x, acc[3][0]); acc[3][1] = fma2(a3, bv.y, acc[3][1]);
        }
    }

    // diagonal export: block covers rows [64bi,64bi+64), cols [32bj,32bj+32);
    // diagonal present iff bj>>1 == bi; thread holds it iff ty == 8*(bj&1)+tx,
    // element r is component r of the output float4 (since r==q on diagonal).
    bool diag = ((bj >> 1) == bi) && (ty == (((bj & 1) << 3) + tx));

    float* dst = g_part[z];
    #pragma unroll
    for (int r = 0; r < 4; r++) {
        float2 p0 = unpk(acc[r][0]);
        float2 p1 = unpk(acc[r][1]);
        float4 o;
        o.x = p0.x; o.y = p0.y; o.z = p1.x; o.w = p1.y;
        *(float4*)&dst[(size_t)(bi * 64 + 4 * ty + r) * NS + bj * 32 + 4 * tx] = o;
        if (diag) {
            float dval = (r == 0) ? o.x : (r == 1) ? o.y : (r == 2) ? o.z : o.w;
            g_diag[z][bi * 64 + 4 * ty + r] = dval;
        }
    }
}

// ---------------- kernel 2: per-anchor loss + fused finalize ----------------
// one block per anchor i, 256 threads. Thread t owns columns [2t, 2t+2).
// Inner loop: 2 threads per positive (j-range split in half), shfl-combined.
__global__ void __launch_bounds__(256) loss_kernel(const float* __restrict__ dist_raw,
                                                   const int* __restrict__ target,
                                                   float* __restrict__ out) {
    __shared__ __align__(16) float bvals[NS];  // cos[i,j]+margin, or -1e30
    __shared__ __align__(16) float rns[NS];    // 1/max(||x_j||, 1e-8)
    __shared__ float crow[NS];
    __shared__ float cps[NS];
    __shared__ int klist[NS];
    __shared__ float cls_pos[NC];
    __shared__ int kcnt, scount;
    __shared__ float red_s[8];
    __shared__ int red_n[8];

    int i = blockIdx.x;
    int t = threadIdx.x;
    int c0 = 2 * t;

    if (t == 0) {
        kcnt = 0; scount = 0;
        float c = 0.f;
        cls_pos[0] = 0.f;
        #pragma unroll
        for (int q = 0; q < NC - 1; q++) {
            c += log1pf(expf(dist_raw[q]));  // softplus cumsum
            cls_pos[q + 1] = c;
        }
    }

    // reconstruct 1/norm from compact diagonal partials (coalesced float2)
    float rj0, rj1;
    {
        float sx = 0.f, sy = 0.f;
        #pragma unroll
        for (int z = 0; z < KSPLIT; z++) {
            float2 p = *(const float2*)&g_diag[z][c0];
            sx += p.x; sy += p.y;
        }
        rj0 = 1.0f / fmaxf(sqrtf(sx), 1e-8f);
        rj1 = 1.0f / fmaxf(sqrtf(sy), 1e-8f);
        rns[c0] = rj0;
        rns[c0 + 1] = rj1;
    }
    __syncthreads();

    // cos row i: sum 8 K-partials, scale by rn_i*rn_j
    float ri = rns[i];
    {
        size_t off = (size_t)i * NS + c0;
        float sx = 0.f, sy = 0.f;
        #pragma unroll
        for (int z = 0; z < KSPLIT; z++) {
            float2 p = *(const float2*)&g_part[z][off];
            sx += p.x; sy += p.y;
        }
        crow[c0] = sx * ri * rj0;
        crow[c0 + 1] = sy * ri * rj1;
        int2 tg = *(const int2*)&target[c0];
        cps[c0] = cls_pos[tg.x];
        cps[c0 + 1] = cls_pos[tg.y];
    }
    __syncthreads();

    float cpi = cps[i];
    int myc = 0;
    #pragma unroll
    for (int q = 0; q < 2; q++) {
        int j = c0 + q;
        float m = fabsf(cpi - cps[j]);
        bool same = (m == 0.0f);  // class_pos strictly increasing -> equality iff same class
        bvals[j] = same ? -1e30f : (crow[j] + m);
        if (same) {
            myc++;
            if (j != i) klist[atomicAdd(&kcnt, 1)] = j;
        }
    }
    atomicAdd(&scount, myc);
    __syncthreads();

    int nk = kcnt;
    int negc = NS - scount;
    float inv = 1.0f / (float)(negc > 1 ? negc : 1);

    float lsum = 0.f;
    int lnz = 0;
    const float4* bv4 = (const float4*)bvals;
    // 2 threads per positive: thread pair (2m, 2m+1) splits j-range in halves.
    int iters = (2 * nk + 255) >> 8;   // uniform trip count for shfl safety
    for (int it = 0; it < iters; it++) {
        int p2 = t + (it << 8);
        bool active = p2 < 2 * nk;
        int pid = active ? (p2 >> 1) : 0;
        int half = p2 & 1;
        float cik = crow[klist[pid]];
        const float4* bp = bv4 + half * 64;   // 64 float4 = 256 j per half
        float acc0 = 0.f, acc1 = 0.f;
        #pragma unroll 8
        for (int jj = 0; jj < 64; jj++) {
            float4 bv = bp[jj];
            acc0 += fmaxf(bv.x - cik, 0.f) + fmaxf(bv.y - cik, 0.f);
            acc1 += fmaxf(bv.z - cik, 0.f) + fmaxf(bv.w - cik, 0.f);
        }
        float acc = acc0 + acc1;
        acc += __shfl_xor_sync(0xffffffffu, acc, 1);   // combine halves
        if (active && half == 0) {
            lsum += acc * inv;
            lnz += (acc != 0.f) ? 1 : 0;
        }
    }

    // block reduce (8 warps)
    for (int o = 16; o > 0; o >>= 1) {
        lsum += __shfl_down_sync(0xffffffffu, lsum, o);
        lnz += __shfl_down_sync(0xffffffffu, lnz, o);
    }
    int wid = t >> 5, lid = t & 31;
    if (lid == 0) { red_s[wid] = lsum; red_n[wid] = lnz; }
    __syncthreads();

    // fused finalize: last block to finish computes the output
    if (t == 0) {
        float bs = 0.f; int bn = 0;
        #pragma unroll
        for (int w = 0; w < 8; w++) { bs += red_s[w]; bn += red_n[w]; }
        atomicAdd(&g_sum, bs);
        atomicAdd(&g_nz, bn);
        __threadfence();
        if (atomicAdd(&g_done, 1) == NS - 1) {
            __threadfence();
            float S = *(volatile float*)&g_sum;
            int N = *(volatile int*)&g_nz;
            out[0] = S / (float)(N > 1 ? N : 1);
        }
    }
}

extern "C" void kernel_launch(void* const* d_in, const int* in_sizes, int n_in,
                              void* d_out, int out_size) {
    const float* pred = (const float*)d_in[0];   // [512, 512] f32
    const float* draw = (const float*)d_in[1];   // [4] f32
    const int* target = (const int*)d_in[2];     // [512] i32
    float* out = (float*)d_out;

    gemm_kernel<<<dim3(16, 8, KSPLIT), 128>>>(pred);
    loss_kernel<<<NS, 256>>>(draw, target, out);
}